// round 11
// baseline (speedup 1.0000x reference)
#include <cuda_runtime.h>
#include <cuda_bf16.h>
#include <math.h>

// DynamicVoxelizer: B=8, N=1e6, C=4.  (bitwise-exact vs XLA reference, R5)
// Output layout (float32):
//   [0)          points_out    32,000,000
//   [32000000)   voxel_coords  24,000,000  (z,y,x; -1 if invalid)
//   [56000000)   point_idxes    8,000,000  (n in batch; -1 if invalid)
//   [64000000)   point_offsets 24,000,000  (xyz - center; 0 if invalid)
//   [88000000)   valid          8,000,000  (1.0/0.0)
//
// NUMERICS: XLA rewrites (x - pmin)/vs -> (x - pmin)*rn(1/vs);
// rn(1/0.1f)==10.0f, rn(1/0.2f)==5.0f exactly. Explicit __fmul_rn/__fadd_rn
// reproduce the reference bit-exactly (rel_err == 0.0, R5/R7/R8/R9).
//
// PERF (R10): R9 structure (2 pts/thread, 256-bit v8 ld/st, dense 32B/lane,
// smem-staged drains) + streaming qualifiers: ld.global.nc.cs on the input,
// st.global.cs on all outputs — evict-first L2 insertion for read-once /
// write-once streams against the 126MB L2.

#define BN_TOTAL   8000000
#define N_PER_B    1000000
#define BLK        256
#define PTS_BLK    (BLK * 2)            // 512 points per block
#define O_COORDS   32000000ull
#define O_IDX      56000000ull
#define O_OFFS     64000000ull
#define O_VALID    88000000ull

// smem layout (floats): coords[0,1536) offs[1536,3072) idx[3072,3584) valid[3584,4096)
#define S_COORDS   0
#define S_OFFS     1536
#define S_IDX      3072
#define S_VALID    3584

__device__ __forceinline__ void ldg256_nc_cs(const float* p, float4& a, float4& b)
{
    asm volatile("ld.global.nc.cs.v8.f32 {%0,%1,%2,%3,%4,%5,%6,%7}, [%8];"
        : "=f"(a.x), "=f"(a.y), "=f"(a.z), "=f"(a.w),
          "=f"(b.x), "=f"(b.y), "=f"(b.z), "=f"(b.w)
        : "l"(p));
}

__device__ __forceinline__ void stg256_cs(float* p, float4 a, float4 b)
{
    asm volatile("st.global.cs.v8.f32 [%0], {%1,%2,%3,%4,%5,%6,%7,%8};"
        :: "l"(p),
           "f"(a.x), "f"(a.y), "f"(a.z), "f"(a.w),
           "f"(b.x), "f"(b.y), "f"(b.z), "f"(b.w)
        : "memory");
}

__global__ __launch_bounds__(BLK)
void voxelizer_kernel(const float* __restrict__ pts, float* __restrict__ out)
{
    __shared__ float s[4096];   // 16 KB

    const int tid = threadIdx.x;
    const int b   = blockIdx.x;
    const int t   = b * BLK + tid;          // thread over 4M threads
    const int j0  = 2 * t;                  // first of two points

    // ---- 256-bit input load: 2 points (32B), dense across the warp ----
    float4 p0, p1;
    ldg256_nc_cs(pts + 8ull * (unsigned)t, p0, p1);

    float4 po[2];
    #pragma unroll
    for (int k = 0; k < 2; k++) {
        float4 p = k ? p1 : p0;
        bool nn = !(isnan(p.x) || isnan(p.y) || isnan(p.z) || isnan(p.w));

        // cf = floor((xyz - pmin) * rn(1/vs)); rn(1/0.1f)=10.0f, rn(1/0.2f)=5.0f
        float fx = floorf(__fmul_rn(__fadd_rn(p.x, 51.2f), 10.0f));
        float fy = floorf(__fmul_rn(__fadd_rn(p.y, 51.2f), 10.0f));
        float fz = floorf(__fmul_rn(__fadd_rn(p.z,  5.0f),  5.0f));

        bool in_range = (fx >= 0.0f) & (fx < 1024.0f)
                      & (fy >= 0.0f) & (fy < 1024.0f)
                      & (fz >= 0.0f) & (fz < 40.0f);
        bool valid = nn && in_range;

        // centers = (cf*vs + pmin) + vs*0.5, exact f32, reference op order
        float cxc = __fadd_rn(__fadd_rn(__fmul_rn(fx, 0.1f), -51.2f), 0.05f);
        float cyc = __fadd_rn(__fadd_rn(__fmul_rn(fy, 0.1f), -51.2f), 0.05f);
        float czc = __fadd_rn(__fadd_rn(__fmul_rn(fz, 0.2f),  -5.0f), 0.1f);

        po[k] = valid ? p : make_float4(0.f, 0.f, 0.f, 0.f);

        int c6 = 6 * tid + 3 * k;
        s[S_COORDS + c6 + 0] = valid ? fz : -1.0f;
        s[S_COORDS + c6 + 1] = valid ? fy : -1.0f;
        s[S_COORDS + c6 + 2] = valid ? fx : -1.0f;

        s[S_OFFS + c6 + 0] = valid ? __fadd_rn(p.x, -cxc) : 0.0f;
        s[S_OFFS + c6 + 1] = valid ? __fadd_rn(p.y, -cyc) : 0.0f;
        s[S_OFFS + c6 + 2] = valid ? __fadd_rn(p.z, -czc) : 0.0f;

        // j0 and j0+1 always share a batch (boundaries are even)
        int j = j0 + k;
        int n = j - (j / N_PER_B) * N_PER_B;
        s[S_IDX   + 2 * tid + k] = valid ? (float)n : -1.0f;
        s[S_VALID + 2 * tid + k] = valid ? 1.0f : 0.0f;
    }

    // ---- points_out: one 256-bit store (dense, evict-first) ----
    stg256_cs(out + 8ull * (unsigned)t, po[0], po[1]);

    __syncthreads();

    // ---- drain: 4096 floats = 512 x 32B chunks per block, 2 per thread ----
    const unsigned ub = (unsigned)b;
    #pragma unroll
    for (int pass = 0; pass < 2; pass++) {
        int q = tid + pass * BLK;           // 0..511
        const float* src;
        float* dst;
        if (q < 192) {
            src = &s[S_COORDS + 8 * q];
            dst = out + O_COORDS + 1536ull * ub + 8 * q;
        } else if (q < 384) {
            int q2 = q - 192;
            src = &s[S_OFFS + 8 * q2];
            dst = out + O_OFFS + 1536ull * ub + 8 * q2;
        } else if (q < 448) {
            int q2 = q - 384;
            src = &s[S_IDX + 8 * q2];
            dst = out + O_IDX + 512ull * ub + 8 * q2;
        } else {
            int q2 = q - 448;
            src = &s[S_VALID + 8 * q2];
            dst = out + O_VALID + 512ull * ub + 8 * q2;
        }
        float4 a = *reinterpret_cast<const float4*>(src);
        float4 c = *reinterpret_cast<const float4*>(src + 4);
        stg256_cs(dst, a, c);
    }
}

extern "C" void kernel_launch(void* const* d_in, const int* in_sizes, int n_in,
                              void* d_out, int out_size)
{
    const float* pts = (const float*)d_in[0];
    float* out = (float*)d_out;
    voxelizer_kernel<<<BN_TOTAL / PTS_BLK, BLK>>>(pts, out);
}